// round 9
// baseline (speedup 1.0000x reference)
#include <cuda_runtime.h>
#include <cstdint>

// x: [B=8, Ci=32, T=128, X=256, P=3] f32
// w*: [Ci=32, Co=32, 16, 16, 3] f32
// out: [8, 32, 128, 256, 3] f32
#define B_  8
#define CI_ 32
#define CO_ 32
#define T_  128
#define X_  256
#define P_  3
#define KX_ 16
#define KT_ 32
#define KP_ 2

__device__ float2 g_A[B_*CI_*KX_*KP_*T_];   // [bci][kx][kp][t]
__device__ float2 g_C[KT_*KX_*KP_*B_*CI_];  // [mode][bci]
__device__ float2 g_D[B_*CO_*KT_*KX_*KP_];  // [bco][mode]
__device__ float2 g_H[B_*CO_*T_*KX_*KP_];   // [bco][t][rem]

__device__ __forceinline__ float2 cmulf(float2 a, float2 b) {
    return make_float2(a.x*b.x - a.y*b.y, a.x*b.y + a.y*b.x);
}

// In-register radix-2 FFT-16. SGN=-1: forward; SGN=+1: inverse (unscaled).
template<int SGN>
__device__ __forceinline__ void fft16(float2 v[16]) {
    float2 tmp;
#define SW_(i,j) { tmp=v[i]; v[i]=v[j]; v[j]=tmp; }
    SW_(1,8) SW_(2,4) SW_(3,12) SW_(5,10) SW_(7,14) SW_(11,13)
#undef SW_
    const float Ct[8] = {1.f, 0.92387953251f, 0.70710678119f, 0.38268343236f,
                         0.f, -0.38268343236f, -0.70710678119f, -0.92387953251f};
    const float St[8] = {0.f, 0.38268343236f, 0.70710678119f, 0.92387953251f,
                         1.f, 0.92387953251f, 0.70710678119f, 0.38268343236f};
#pragma unroll
    for (int m = 2; m <= 16; m <<= 1) {
        const int half = m >> 1;
        const int step = 16 / m;
#pragma unroll
        for (int k0 = 0; k0 < 16; k0 += m) {
#pragma unroll
            for (int j = 0; j < half; j++) {
                float2 wt = make_float2(Ct[j*step], (float)SGN * St[j*step]);
                float2 t = cmulf(v[k0+j+half], wt);
                float2 u = v[k0+j];
                v[k0+j]      = make_float2(u.x + t.x, u.y + t.y);
                v[k0+j+half] = make_float2(u.x - t.x, u.y - t.y);
            }
        }
    }
}

// ---------------------------------------------------------------------------
// K1: forward P-stage (rfft3 -> 2 modes) + pruned X-DFT (256 -> 16 modes)
// ---------------------------------------------------------------------------
__global__ void __launch_bounds__(256) k_fwd_px(const float* __restrict__ x) {
    __shared__ float2 region[8][544];
    __shared__ float2 tw[256];          // e^{-2pi i n/256}
    __shared__ float2 outstage[8][32];

    const int tid = threadIdx.x;
    {
        float sv, cv;
        __sincosf(-6.283185307179586f * (float)tid * (1.0f/256.0f), &sv, &cv);
        tw[tid] = make_float2(cv, sv);
    }
    const int bci = blockIdx.x >> 4;
    const int t0  = (blockIdx.x & 15) << 3;

    const float4* src = (const float4*)(x + (size_t)(bci*T_ + t0) * (X_*P_));
#pragma unroll
    for (int i = 0; i < 6; i++) {
        int idx = tid + i*256;
        float4 vv = src[idx];
        int fl = idx * 4;
        int line = fl / 768, off = fl % 768;
        *(float4*)((float*)region + line*1088 + off) = vv;
    }
    __syncthreads();

    const int w  = tid >> 5;
    const int ln = tid & 31;
    const int b_ = ln & 15;
    const int kp = ln >> 4;

    const float* rp = (const float*)region[w];
    float2 v[16];
#pragma unroll
    for (int a = 0; a < 16; a++) {
        int base = (a*16 + b_) * 3;
        float xa = rp[base], xb = rp[base+1], xc = rp[base+2];
        if (kp == 0) v[a] = make_float2(xa + xb + xc, 0.f);
        else         v[a] = make_float2(xa - 0.5f*(xb+xc), 0.8660254037844386f*(xc - xb));
    }
    __syncwarp();
    fft16<-1>(v);

    float2* trb = region[w];
#pragma unroll
    for (int k = 0; k < 16; k++) {
        float2 z = cmulf(v[k], tw[b_*k]);
        trb[b_*33 + kp*16 + k] = z;
    }
    __syncwarp();

    const int ko = ln & 15, kpo = ln >> 4;
    float2 acc = make_float2(0.f, 0.f);
#pragma unroll
    for (int b = 0; b < 16; b++) {
        float2 z = trb[b*33 + kpo*16 + ko];
        acc.x += z.x; acc.y += z.y;
    }
    outstage[w][ln] = acc;
    __syncthreads();

    const int idx = tid >> 3;
    const int tt  = tid & 7;
    const int k   = idx & 15, kpp = idx >> 4;
    g_A[(((size_t)bci*KX_ + k)*KP_ + kpp)*T_ + t0 + tt] = outstage[tt][kpp*16 + k];
}

// ---------------------------------------------------------------------------
// K2: forward T-DFT (128 -> 32 corner modes), radix split T = 8a + b.
// Block = half a bci (16 lines), 128 threads, grid 512.
// ---------------------------------------------------------------------------
__global__ void __launch_bounds__(128) k_fwd_t() {
    __shared__ float2 tab[128];       // e^{-2pi i n/128}
    __shared__ float2 reg[4][544];
    const int tid = threadIdx.x;
    {
        float sv, cv;
        __sincosf(-6.283185307179586f * (float)tid * (1.0f/128.0f), &sv, &cv);
        tab[tid] = make_float2(cv, sv);
    }
    const int bci = blockIdx.x >> 1;
    const int h   = blockIdx.x & 1;

    const float4* src = (const float4*)(g_A + ((size_t)bci*32 + h*16)*128);
#pragma unroll
    for (int i = 0; i < 8; i++) {
        int idx = tid + i*128;
        float4 vv = src[idx];
        int f2i = idx*2;
        int line = f2i >> 7, t = f2i & 127;
        *(float4*)&reg[line>>2][(line&3)*136 + t] = vv;
    }
    __syncthreads();

    const int w = tid >> 5, ln = tid & 31;
    const int l = ln >> 3, b = ln & 7;
    float2* R = reg[w];

    float2 v[16];
#pragma unroll
    for (int a = 0; a < 16; a++) v[a] = R[l*136 + a*8 + b];
    __syncwarp();
    fft16<-1>(v);
#pragma unroll
    for (int k = 0; k < 16; k++) R[ln*17 + k] = v[k];
    __syncwarp();

    const int o  = ln;
    const int f  = (o < 16) ? o : (o + 96);
    const int km = o & 15;
    float2 acc[4];
#pragma unroll
    for (int q = 0; q < 4; q++) acc[q] = make_float2(0.f, 0.f);
#pragma unroll
    for (int bb = 0; bb < 8; bb++) {
        float2 twv = tab[(bb*f) & 127];
#pragma unroll
        for (int q = 0; q < 4; q++) {
            float2 z = R[(q*8 + bb)*17 + km];
            acc[q].x += z.x*twv.x - z.y*twv.y;
            acc[q].y += z.x*twv.y + z.y*twv.x;
        }
    }
#pragma unroll
    for (int q = 0; q < 4; q++) {
        int rem = h*16 + w*4 + q;
        g_C[((size_t)o*32 + rem)*256 + bci] = acc[q];
    }
}

// ---------------------------------------------------------------------------
// K3: einsum reading RAW weights. Block = (kt,kx), computes both kp modes.
// D[bco][m] = (1/TX) sum_ci C[m][b,ci] * W[m][ci,co], m = m0, m0+1.
// The two kp weights are adjacent floats -> one sector serves both modes.
// ---------------------------------------------------------------------------
__global__ void __launch_bounds__(256) k_einsum(const float* __restrict__ w1r, const float* __restrict__ w1i,
                                               const float* __restrict__ w2r, const float* __restrict__ w2i) {
    __shared__ float2 Cs[2][256];
    __shared__ float2 Ws[2][1024];
    const int tid = threadIdx.x;
    const int kt = blockIdx.x >> 4;       // 0..31
    const int kx = blockIdx.x & 15;
    const int m0 = kt*32 + kx*2;
    const float* wr; const float* wi;
    if (kt < 16) { wr = w1r; wi = w1i; }
    else         { wr = w2r; wi = w2i; }
    const int ktw = kt & 15;

    Cs[0][tid] = g_C[(size_t)m0*256 + tid];
    Cs[1][tid] = g_C[(size_t)(m0+1)*256 + tid];
#pragma unroll
    for (int i = 0; i < 4; i++) {
        int e = tid + i*256;                    // e = ci*32+co
        size_t base = (size_t)e*768 + (ktw*16 + kx)*3;
        Ws[0][e] = make_float2(__ldg(wr + base),     __ldg(wi + base));
        Ws[1][e] = make_float2(__ldg(wr + base + 1), __ldg(wi + base + 1));
    }
    __syncthreads();

    const int b = tid >> 5, co = tid & 31;
    float2 a0 = make_float2(0.f, 0.f);
    float2 a1 = make_float2(0.f, 0.f);
#pragma unroll
    for (int ci = 0; ci < 32; ci++) {
        float2 c0 = Cs[0][b*32 + ci];
        float2 c1 = Cs[1][b*32 + ci];
        float2 q0 = Ws[0][ci*32 + co];
        float2 q1 = Ws[1][ci*32 + co];
        a0.x += c0.x*q0.x - c0.y*q0.y;
        a0.y += c0.x*q0.y + c0.y*q0.x;
        a1.x += c1.x*q1.x - c1.y*q1.y;
        a1.y += c1.x*q1.y + c1.y*q1.x;
    }
    const float S = 1.0f / (128.0f * 256.0f);
    *(float4*)(g_D + (size_t)tid*1024 + m0) = make_float4(a0.x*S, a0.y*S, a1.x*S, a1.y*S);
}

// ---------------------------------------------------------------------------
// K4: inverse T (32 corner modes -> 128 t), radix split t = 8a + b.
// Block = half a bco (16 rem lines), 128 threads, grid 512.
// ---------------------------------------------------------------------------
__global__ void __launch_bounds__(128) k_inv_t() {
    __shared__ float2 tab[128];       // e^{+2pi i n/128}
    __shared__ float2 Ds[16][33];
    __shared__ float2 Hs[128][17];
    const int tid = threadIdx.x;
    {
        float sv, cv;
        __sincosf(6.283185307179586f * (float)tid * (1.0f/128.0f), &sv, &cv);
        tab[tid] = make_float2(cv, sv);
    }
    const int bco = blockIdx.x >> 1;
    const int h   = blockIdx.x & 1;

    const float2* src = g_D + (size_t)bco*1024;
#pragma unroll
    for (int i = 0; i < 4; i++) {
        int idx = tid + i*128;
        int j = idx >> 4, r = idx & 15;
        Ds[r][j] = src[j*32 + h*16 + r];
    }
    __syncthreads();

    const int w = tid >> 5, ln = tid & 31;
    const int l = ln >> 3, b = ln & 7;
    const int rem = w*4 + l;

    float2 S[16];
#pragma unroll
    for (int r = 0; r < 16; r++) {
        float2 d0 = Ds[rem][r];
        float2 d1 = Ds[rem][r+16];
        float2 t0 = tab[(b*r) & 127];
        float2 t1 = tab[(b*(r+112)) & 127];
        S[r].x = d0.x*t0.x - d0.y*t0.y + d1.x*t1.x - d1.y*t1.y;
        S[r].y = d0.x*t0.y + d0.y*t0.x + d1.x*t1.y + d1.y*t1.x;
    }
    fft16<1>(S);
#pragma unroll
    for (int a = 0; a < 16; a++) Hs[a*8 + b][rem] = S[a];
    __syncthreads();

    float4* dst = (float4*)(g_H + (size_t)bco*4096);
#pragma unroll
    for (int i = 0; i < 8; i++) {
        int idx = tid + i*128;
        int t = idx >> 3, q = idx & 7;
        float2 a0 = Hs[t][q*2], a1 = Hs[t][q*2 + 1];
        dst[t*16 + h*8 + q] = make_float4(a0.x, a0.y, a1.x, a1.y);
    }
}

// ---------------------------------------------------------------------------
// K5: inverse X (16 modes -> 256 x) + irfft over P, permuted store staging.
// ---------------------------------------------------------------------------
__global__ void __launch_bounds__(256) k_inv_xp(float* __restrict__ out) {
    __shared__ float2 tw[256];        // e^{+2pi i n/256}
    __shared__ float2 Hsm[8][32];
    __shared__ float2 gb[8][2][264];
    const int tid = threadIdx.x;
    {
        float sv, cv;
        __sincosf(6.283185307179586f * (float)tid * (1.0f/256.0f), &sv, &cv);
        tw[tid] = make_float2(cv, sv);
    }
    const int bco = blockIdx.x >> 4;
    const int t0  = (blockIdx.x & 15) << 3;
    Hsm[tid>>5][tid&31] = g_H[((size_t)bco*T_ + t0 + (tid>>5))*32 + (tid&31)];
    __syncthreads();

    const int w  = tid >> 5;
    const int ln = tid & 31;
    const int b_ = ln & 15;
    const int kp = ln >> 4;

    float2 v[16];
#pragma unroll
    for (int k = 0; k < 16; k++)
        v[k] = cmulf(Hsm[w][k*2 + kp], tw[k*b_]);
    fft16<1>(v);
    const int pbase = (b_ >> 3) + (b_ & 7)*33;
#pragma unroll
    for (int a = 0; a < 16; a++)
        gb[w][kp][pbase + 2*a] = v[a];
    __syncwarp();

    float f[24];
    const float TH = 1.0f / 3.0f;
    const float SQ3 = 1.7320508075688772f;
#pragma unroll
    for (int j = 0; j < 8; j++) {
        float2 g0 = gb[w][0][ln + 33*j];
        float2 g1 = gb[w][1][ln + 33*j];
        float r = g0.x;
        f[3*j+0] = (r + 2.f*g1.x) * TH;
        f[3*j+1] = (r - g1.x - SQ3*g1.y) * TH;
        f[3*j+2] = (r - g1.x + SQ3*g1.y) * TH;
    }
    float4* op = (float4*)(out + ((size_t)bco*T_ + t0 + w)*768 + 24*ln);
#pragma unroll
    for (int q = 0; q < 6; q++)
        op[q] = make_float4(f[4*q], f[4*q+1], f[4*q+2], f[4*q+3]);
}

extern "C" void kernel_launch(void* const* d_in, const int* in_sizes, int n_in,
                              void* d_out, int out_size) {
    const float* x   = (const float*)d_in[0];
    const float* w1r = (const float*)d_in[1];
    const float* w1i = (const float*)d_in[2];
    const float* w2r = (const float*)d_in[3];
    const float* w2i = (const float*)d_in[4];
    float* out = (float*)d_out;

    k_fwd_px<<<4096, 256>>>(x);
    k_fwd_t <<<512, 128>>>();
    k_einsum<<<512, 256>>>(w1r, w1i, w2r, w2i);
    k_inv_t <<<512, 128>>>();
    k_inv_xp<<<4096, 256>>>(out);
}

// round 10
// speedup vs baseline: 1.0032x; 1.0032x over previous
#include <cuda_runtime.h>
#include <cstdint>

// x: [B=8, Ci=32, T=128, X=256, P=3] f32
// w*: [Ci=32, Co=32, 16, 16, 3] f32
// out: [8, 32, 128, 256, 3] f32
#define B_  8
#define CI_ 32
#define CO_ 32
#define T_  128
#define X_  256
#define P_  3
#define KX_ 16
#define KT_ 32
#define KP_ 2

__device__ float2 g_A[B_*CI_*KX_*KP_*T_];   // [bci][kx][kp][t]
__device__ float2 g_C[KT_*KX_*KP_*B_*CI_];  // [mode][bci]
__device__ float2 g_D[B_*CO_*KT_*KX_*KP_];  // [bco][mode]
__device__ float2 g_W[1024*1024];           // [mode][e=ci*32+co]

__device__ __forceinline__ float2 cmulf(float2 a, float2 b) {
    return make_float2(a.x*b.x - a.y*b.y, a.x*b.y + a.y*b.x);
}

// In-register radix-2 FFT-16. SGN=-1: forward; SGN=+1: inverse (unscaled).
template<int SGN>
__device__ __forceinline__ void fft16(float2 v[16]) {
    float2 tmp;
#define SW_(i,j) { tmp=v[i]; v[i]=v[j]; v[j]=tmp; }
    SW_(1,8) SW_(2,4) SW_(3,12) SW_(5,10) SW_(7,14) SW_(11,13)
#undef SW_
    const float Ct[8] = {1.f, 0.92387953251f, 0.70710678119f, 0.38268343236f,
                         0.f, -0.38268343236f, -0.70710678119f, -0.92387953251f};
    const float St[8] = {0.f, 0.38268343236f, 0.70710678119f, 0.92387953251f,
                         1.f, 0.92387953251f, 0.70710678119f, 0.38268343236f};
#pragma unroll
    for (int m = 2; m <= 16; m <<= 1) {
        const int half = m >> 1;
        const int step = 16 / m;
#pragma unroll
        for (int k0 = 0; k0 < 16; k0 += m) {
#pragma unroll
            for (int j = 0; j < half; j++) {
                float2 wt = make_float2(Ct[j*step], (float)SGN * St[j*step]);
                float2 t = cmulf(v[k0+j+half], wt);
                float2 u = v[k0+j];
                v[k0+j]      = make_float2(u.x + t.x, u.y + t.y);
                v[k0+j+half] = make_float2(u.x - t.x, u.y - t.y);
            }
        }
    }
}

// ---------------------------------------------------------------------------
// K0: weight transpose -> g_W[mode][e], coalesced writes.
// ---------------------------------------------------------------------------
__global__ void __launch_bounds__(256) k_wt(const float* __restrict__ w1r, const float* __restrict__ w1i,
                                           const float* __restrict__ w2r, const float* __restrict__ w2i) {
    __shared__ float sre[32][49];
    __shared__ float sim[32][49];
    const int kt = blockIdx.x;          // 0..31
    const int e0 = blockIdx.y * 32;
    const float* wr = (kt < 16) ? w1r : w2r;
    const float* wi = (kt < 16) ? w1i : w2i;
    const int ktw = kt & 15;
    const int tid = threadIdx.x;
    for (int j = tid; j < 32*48; j += 256) {
        int el = j / 48, m = j % 48;
        size_t src = (size_t)(e0 + el)*768 + ktw*48 + m;
        sre[el][m] = wr[src];
        sim[el][m] = wi[src];
    }
    __syncthreads();
    for (int idx = tid; idx < 1024; idx += 256) {
        int ml = idx >> 5, el = idx & 31;    // ml = kx*2+kp
        int kx = ml >> 1, kp = ml & 1;
        int m = kx*3 + kp;
        g_W[((size_t)kt*32 + ml)*1024 + e0 + el] = make_float2(sre[el][m], sim[el][m]);
    }
}

// ---------------------------------------------------------------------------
// K1: forward P-stage (rfft3 -> 2 modes) + pruned X-DFT (256 -> 16 modes)
// ---------------------------------------------------------------------------
__global__ void __launch_bounds__(256) k_fwd_px(const float* __restrict__ x) {
    __shared__ float2 region[8][544];
    __shared__ float2 tw[256];          // e^{-2pi i n/256}
    __shared__ float2 outstage[8][32];

    const int tid = threadIdx.x;
    {
        float sv, cv;
        __sincosf(-6.283185307179586f * (float)tid * (1.0f/256.0f), &sv, &cv);
        tw[tid] = make_float2(cv, sv);
    }
    const int bci = blockIdx.x >> 4;
    const int t0  = (blockIdx.x & 15) << 3;

    const float4* src = (const float4*)(x + (size_t)(bci*T_ + t0) * (X_*P_));
#pragma unroll
    for (int i = 0; i < 6; i++) {
        int idx = tid + i*256;
        float4 vv = src[idx];
        int fl = idx * 4;
        int line = fl / 768, off = fl % 768;
        *(float4*)((float*)region + line*1088 + off) = vv;
    }
    __syncthreads();

    const int w  = tid >> 5;
    const int ln = tid & 31;
    const int b_ = ln & 15;
    const int kp = ln >> 4;

    const float* rp = (const float*)region[w];
    float2 v[16];
#pragma unroll
    for (int a = 0; a < 16; a++) {
        int base = (a*16 + b_) * 3;
        float xa = rp[base], xb = rp[base+1], xc = rp[base+2];
        if (kp == 0) v[a] = make_float2(xa + xb + xc, 0.f);
        else         v[a] = make_float2(xa - 0.5f*(xb+xc), 0.8660254037844386f*(xc - xb));
    }
    __syncwarp();
    fft16<-1>(v);

    float2* trb = region[w];
#pragma unroll
    for (int k = 0; k < 16; k++) {
        float2 z = cmulf(v[k], tw[b_*k]);
        trb[b_*33 + kp*16 + k] = z;
    }
    __syncwarp();

    const int ko = ln & 15, kpo = ln >> 4;
    float2 acc = make_float2(0.f, 0.f);
#pragma unroll
    for (int b = 0; b < 16; b++) {
        float2 z = trb[b*33 + kpo*16 + ko];
        acc.x += z.x; acc.y += z.y;
    }
    outstage[w][ln] = acc;
    __syncthreads();

    const int idx = tid >> 3;
    const int tt  = tid & 7;
    const int k   = idx & 15, kpp = idx >> 4;
    g_A[(((size_t)bci*KX_ + k)*KP_ + kpp)*T_ + t0 + tt] = outstage[tt][kpp*16 + k];
}

// ---------------------------------------------------------------------------
// K2: forward T-DFT (128 -> 32 corner modes), radix split T = 8a + b.
// Block = half a bci (16 lines), 128 threads, grid 512.
// ---------------------------------------------------------------------------
__global__ void __launch_bounds__(128) k_fwd_t() {
    __shared__ float2 tab[128];       // e^{-2pi i n/128}
    __shared__ float2 reg[4][544];
    const int tid = threadIdx.x;
    {
        float sv, cv;
        __sincosf(-6.283185307179586f * (float)tid * (1.0f/128.0f), &sv, &cv);
        tab[tid] = make_float2(cv, sv);
    }
    const int bci = blockIdx.x >> 1;
    const int h   = blockIdx.x & 1;

    const float4* src = (const float4*)(g_A + ((size_t)bci*32 + h*16)*128);
#pragma unroll
    for (int i = 0; i < 8; i++) {
        int idx = tid + i*128;
        float4 vv = src[idx];
        int f2i = idx*2;
        int line = f2i >> 7, t = f2i & 127;
        *(float4*)&reg[line>>2][(line&3)*136 + t] = vv;
    }
    __syncthreads();

    const int w = tid >> 5, ln = tid & 31;
    const int l = ln >> 3, b = ln & 7;
    float2* R = reg[w];

    float2 v[16];
#pragma unroll
    for (int a = 0; a < 16; a++) v[a] = R[l*136 + a*8 + b];
    __syncwarp();
    fft16<-1>(v);
#pragma unroll
    for (int k = 0; k < 16; k++) R[ln*17 + k] = v[k];
    __syncwarp();

    const int o  = ln;
    const int f  = (o < 16) ? o : (o + 96);
    const int km = o & 15;
    float2 acc[4];
#pragma unroll
    for (int q = 0; q < 4; q++) acc[q] = make_float2(0.f, 0.f);
#pragma unroll
    for (int bb = 0; bb < 8; bb++) {
        float2 twv = tab[(bb*f) & 127];
#pragma unroll
        for (int q = 0; q < 4; q++) {
            float2 z = R[(q*8 + bb)*17 + km];
            acc[q].x += z.x*twv.x - z.y*twv.y;
            acc[q].y += z.x*twv.y + z.y*twv.x;
        }
    }
#pragma unroll
    for (int q = 0; q < 4; q++) {
        int rem = h*16 + w*4 + q;
        g_C[((size_t)o*32 + rem)*256 + bci] = acc[q];
    }
}

// ---------------------------------------------------------------------------
// K3: coalesced einsum via g_W: D[bco][mode] = (1/TX) sum_ci C[mode][b,ci]W[mode][ci,co]
// ---------------------------------------------------------------------------
__global__ void __launch_bounds__(256) k_einsum() {
    __shared__ float2 Cs[256];
    __shared__ float2 Ws[1024];
    const int tid = threadIdx.x;
    const int mode = blockIdx.x;
    Cs[tid] = g_C[(size_t)mode*256 + tid];
#pragma unroll
    for (int i = 0; i < 4; i++)
        Ws[tid + i*256] = g_W[(size_t)mode*1024 + tid + i*256];
    __syncthreads();
    const int b = tid >> 5, co = tid & 31;
    float2 acc = make_float2(0.f, 0.f);
#pragma unroll
    for (int ci = 0; ci < 32; ci++) {
        float2 c = Cs[b*32 + ci];
        float2 wv = Ws[ci*32 + co];
        acc.x += c.x*wv.x - c.y*wv.y;
        acc.y += c.x*wv.y + c.y*wv.x;
    }
    const float INV_TX = 1.0f / (128.0f * 256.0f);
    g_D[(size_t)tid*1024 + mode] = make_float2(acc.x*INV_TX, acc.y*INV_TX);
}

// ---------------------------------------------------------------------------
// K4: FUSED inverse: T-inverse (32 corner modes -> this block's 8 t-rows)
//     + X-inverse (16 modes -> 256 x) + irfft over P.
// Block = (bco, t0 8-row chunk), grid 4096, 256 threads.
// H[t][rem] = sum_{r<16} D[r*32+rem] w128^{rt} + D[(r+16)*32+rem] w128^{(r+112)t}
// Each (t,rem) of H computed exactly once; only the 8KB D load is shared/L2-hot.
// ---------------------------------------------------------------------------
__global__ void __launch_bounds__(256) k_inv_xp(float* __restrict__ out) {
    __shared__ float2 tw[256];        // e^{+2pi i n/256}
    __shared__ float2 tb[128];        // e^{+2pi i n/128}
    __shared__ float2 Ds[32][33];     // [rem][j]
    __shared__ float2 Hsm[8][32];     // [w][rem]
    __shared__ float2 gb[8][2][264];
    const int tid = threadIdx.x;
    {
        float sv, cv;
        __sincosf(6.283185307179586f * (float)tid * (1.0f/256.0f), &sv, &cv);
        tw[tid] = make_float2(cv, sv);
        if (tid < 128) {
            __sincosf(6.283185307179586f * (float)tid * (1.0f/128.0f), &sv, &cv);
            tb[tid] = make_float2(cv, sv);
        }
    }
    const int bco = blockIdx.x >> 4;
    const int t0  = (blockIdx.x & 15) << 3;

    // load this bco's full D: 1024 f2, coalesced
    const float2* src = g_D + (size_t)bco*1024;
#pragma unroll
    for (int i = 0; i < 4; i++) {
        int idx = tid + i*256;        // idx = j*32 + rem
        Ds[idx & 31][idx >> 5] = src[idx];
    }
    __syncthreads();

    const int w  = tid >> 5;
    const int ln = tid & 31;

    // T-inverse: lane ln computes H[t0+w][rem=ln]
    {
        const int t = t0 + w;
        float2 h = make_float2(0.f, 0.f);
#pragma unroll
        for (int r = 0; r < 16; r++) {
            float2 d0 = Ds[ln][r];
            float2 d1 = Ds[ln][r+16];
            float2 e0 = tb[(r*t) & 127];
            float2 e1 = tb[((r+112)*t) & 127];
            h.x += d0.x*e0.x - d0.y*e0.y + d1.x*e1.x - d1.y*e1.y;
            h.y += d0.x*e0.y + d0.y*e0.x + d1.x*e1.y + d1.y*e1.x;
        }
        Hsm[w][ln] = h;
    }
    __syncwarp();     // warp w only touches Hsm[w][*]

    const int b_ = ln & 15;
    const int kp = ln >> 4;

    float2 v[16];
#pragma unroll
    for (int k = 0; k < 16; k++)
        v[k] = cmulf(Hsm[w][k*2 + kp], tw[k*b_]);
    fft16<1>(v);
    const int pbase = (b_ >> 3) + (b_ & 7)*33;
#pragma unroll
    for (int a = 0; a < 16; a++)
        gb[w][kp][pbase + 2*a] = v[a];
    __syncwarp();

    float f[24];
    const float TH = 1.0f / 3.0f;
    const float SQ3 = 1.7320508075688772f;
#pragma unroll
    for (int j = 0; j < 8; j++) {
        float2 g0 = gb[w][0][ln + 33*j];
        float2 g1 = gb[w][1][ln + 33*j];
        float r = g0.x;
        f[3*j+0] = (r + 2.f*g1.x) * TH;
        f[3*j+1] = (r - g1.x - SQ3*g1.y) * TH;
        f[3*j+2] = (r - g1.x + SQ3*g1.y) * TH;
    }
    float4* op = (float4*)(out + ((size_t)bco*T_ + t0 + w)*768 + 24*ln);
#pragma unroll
    for (int q = 0; q < 6; q++)
        op[q] = make_float4(f[4*q], f[4*q+1], f[4*q+2], f[4*q+3]);
}

extern "C" void kernel_launch(void* const* d_in, const int* in_sizes, int n_in,
                              void* d_out, int out_size) {
    const float* x   = (const float*)d_in[0];
    const float* w1r = (const float*)d_in[1];
    const float* w1i = (const float*)d_in[2];
    const float* w2r = (const float*)d_in[3];
    const float* w2i = (const float*)d_in[4];
    float* out = (float*)d_out;

    k_wt    <<<dim3(32, 32), 256>>>(w1r, w1i, w2r, w2i);
    k_fwd_px<<<4096, 256>>>(x);
    k_fwd_t <<<512, 128>>>();
    k_einsum<<<1024, 256>>>();
    k_inv_xp<<<4096, 256>>>(out);
}

// round 11
// speedup vs baseline: 1.0699x; 1.0665x over previous
#include <cuda_runtime.h>
#include <cstdint>

// x: [B=8, Ci=32, T=128, X=256, P=3] f32
// w*: [Ci=32, Co=32, 16, 16, 3] f32
// out: [8, 32, 128, 256, 3] f32
#define B_  8
#define CI_ 32
#define CO_ 32
#define T_  128
#define X_  256
#define P_  3
#define KX_ 16
#define KT_ 32
#define KP_ 2

__device__ float2 g_A[B_*CI_*KX_*KP_*T_];   // [bci][kx][kp][t]
__device__ float2 g_C[KT_*KX_*KP_*B_*CI_];  // [mode][bci]
__device__ float2 g_D[B_*CO_*KT_*KX_*KP_];  // [bco][mode]
__device__ float2 g_H[B_*CO_*T_*KX_*KP_];   // [bco][t][rem]
__device__ float2 g_W[1024*1024];           // [mode][e=ci*32+co]

__device__ __forceinline__ float2 cmulf(float2 a, float2 b) {
    return make_float2(a.x*b.x - a.y*b.y, a.x*b.y + a.y*b.x);
}

// In-register radix-2 FFT-16. SGN=-1: forward; SGN=+1: inverse (unscaled).
template<int SGN>
__device__ __forceinline__ void fft16(float2 v[16]) {
    float2 tmp;
#define SW_(i,j) { tmp=v[i]; v[i]=v[j]; v[j]=tmp; }
    SW_(1,8) SW_(2,4) SW_(3,12) SW_(5,10) SW_(7,14) SW_(11,13)
#undef SW_
    const float Ct[8] = {1.f, 0.92387953251f, 0.70710678119f, 0.38268343236f,
                         0.f, -0.38268343236f, -0.70710678119f, -0.92387953251f};
    const float St[8] = {0.f, 0.38268343236f, 0.70710678119f, 0.92387953251f,
                         1.f, 0.92387953251f, 0.70710678119f, 0.38268343236f};
#pragma unroll
    for (int m = 2; m <= 16; m <<= 1) {
        const int half = m >> 1;
        const int step = 16 / m;
#pragma unroll
        for (int k0 = 0; k0 < 16; k0 += m) {
#pragma unroll
            for (int j = 0; j < half; j++) {
                float2 wt = make_float2(Ct[j*step], (float)SGN * St[j*step]);
                float2 t = cmulf(v[k0+j+half], wt);
                float2 u = v[k0+j];
                v[k0+j]      = make_float2(u.x + t.x, u.y + t.y);
                v[k0+j+half] = make_float2(u.x - t.x, u.y - t.y);
            }
        }
    }
}

// ---------------------------------------------------------------------------
// K1: forward P-stage + pruned X-DFT  (blocks 0..4095)
//     MERGED weight transpose -> g_W    (blocks 4096..5119, independent work)
// ---------------------------------------------------------------------------
__global__ void __launch_bounds__(256) k_fwd_px(const float* __restrict__ x,
                                               const float* __restrict__ w1r, const float* __restrict__ w1i,
                                               const float* __restrict__ w2r, const float* __restrict__ w2i) {
    __shared__ float2 region[8][544];
    __shared__ float2 tw[256];          // e^{-2pi i n/256}
    __shared__ float2 outstage[8][32];

    const int tid = threadIdx.x;

    if (blockIdx.x >= 4096) {
        // ---- weight transpose branch (was k_wt) ----
        float* sre = (float*)region;            // 32*49 floats
        float* sim = sre + 32*49;
        const int bkt = blockIdx.x - 4096;      // 0..1023
        const int kt = bkt >> 5;
        const int e0 = (bkt & 31) * 32;
        const float* wr = (kt < 16) ? w1r : w2r;
        const float* wi = (kt < 16) ? w1i : w2i;
        const int ktw = kt & 15;
        for (int j = tid; j < 32*48; j += 256) {
            int el = j / 48, m = j % 48;
            size_t src = (size_t)(e0 + el)*768 + ktw*48 + m;
            sre[el*49 + m] = wr[src];
            sim[el*49 + m] = wi[src];
        }
        __syncthreads();
        for (int idx = tid; idx < 1024; idx += 256) {
            int ml = idx >> 5, el = idx & 31;    // ml = kx*2+kp
            int kx = ml >> 1, kp = ml & 1;
            int m = kx*3 + kp;
            g_W[((size_t)kt*32 + ml)*1024 + e0 + el] = make_float2(sre[el*49 + m], sim[el*49 + m]);
        }
        return;
    }

    {
        float sv, cv;
        __sincosf(-6.283185307179586f * (float)tid * (1.0f/256.0f), &sv, &cv);
        tw[tid] = make_float2(cv, sv);
    }
    const int bci = blockIdx.x >> 4;
    const int t0  = (blockIdx.x & 15) << 3;

    const float4* src = (const float4*)(x + (size_t)(bci*T_ + t0) * (X_*P_));
#pragma unroll
    for (int i = 0; i < 6; i++) {
        int idx = tid + i*256;
        float4 vv = src[idx];
        int fl = idx * 4;
        int line = fl / 768, off = fl % 768;
        *(float4*)((float*)region + line*1088 + off) = vv;
    }
    __syncthreads();

    const int w  = tid >> 5;
    const int ln = tid & 31;
    const int b_ = ln & 15;
    const int kp = ln >> 4;

    const float* rp = (const float*)region[w];
    float2 v[16];
#pragma unroll
    for (int a = 0; a < 16; a++) {
        int base = (a*16 + b_) * 3;
        float xa = rp[base], xb = rp[base+1], xc = rp[base+2];
        if (kp == 0) v[a] = make_float2(xa + xb + xc, 0.f);
        else         v[a] = make_float2(xa - 0.5f*(xb+xc), 0.8660254037844386f*(xc - xb));
    }
    __syncwarp();
    fft16<-1>(v);

    float2* trb = region[w];
#pragma unroll
    for (int k = 0; k < 16; k++) {
        float2 z = cmulf(v[k], tw[b_*k]);
        trb[b_*33 + kp*16 + k] = z;
    }
    __syncwarp();

    const int ko = ln & 15, kpo = ln >> 4;
    float2 acc = make_float2(0.f, 0.f);
#pragma unroll
    for (int b = 0; b < 16; b++) {
        float2 z = trb[b*33 + kpo*16 + ko];
        acc.x += z.x; acc.y += z.y;
    }
    outstage[w][ln] = acc;
    __syncthreads();

    const int idx = tid >> 3;
    const int tt  = tid & 7;
    const int k   = idx & 15, kpp = idx >> 4;
    g_A[(((size_t)bci*KX_ + k)*KP_ + kpp)*T_ + t0 + tt] = outstage[tt][kpp*16 + k];
}

// ---------------------------------------------------------------------------
// K2: forward T-DFT (128 -> 32 corner modes), radix split T = 8a + b.
// Block = half a bci (16 lines), 128 threads, grid 512.
// ---------------------------------------------------------------------------
__global__ void __launch_bounds__(128) k_fwd_t() {
    __shared__ float2 tab[128];       // e^{-2pi i n/128}
    __shared__ float2 reg[4][544];
    const int tid = threadIdx.x;
    {
        float sv, cv;
        __sincosf(-6.283185307179586f * (float)tid * (1.0f/128.0f), &sv, &cv);
        tab[tid] = make_float2(cv, sv);
    }
    const int bci = blockIdx.x >> 1;
    const int h   = blockIdx.x & 1;

    const float4* src = (const float4*)(g_A + ((size_t)bci*32 + h*16)*128);
#pragma unroll
    for (int i = 0; i < 8; i++) {
        int idx = tid + i*128;
        float4 vv = src[idx];
        int f2i = idx*2;
        int line = f2i >> 7, t = f2i & 127;
        *(float4*)&reg[line>>2][(line&3)*136 + t] = vv;
    }
    __syncthreads();

    const int w = tid >> 5, ln = tid & 31;
    const int l = ln >> 3, b = ln & 7;
    float2* R = reg[w];

    float2 v[16];
#pragma unroll
    for (int a = 0; a < 16; a++) v[a] = R[l*136 + a*8 + b];
    __syncwarp();
    fft16<-1>(v);
#pragma unroll
    for (int k = 0; k < 16; k++) R[ln*17 + k] = v[k];
    __syncwarp();

    const int o  = ln;
    const int f  = (o < 16) ? o : (o + 96);
    const int km = o & 15;
    float2 acc[4];
#pragma unroll
    for (int q = 0; q < 4; q++) acc[q] = make_float2(0.f, 0.f);
#pragma unroll
    for (int bb = 0; bb < 8; bb++) {
        float2 twv = tab[(bb*f) & 127];
#pragma unroll
        for (int q = 0; q < 4; q++) {
            float2 z = R[(q*8 + bb)*17 + km];
            acc[q].x += z.x*twv.x - z.y*twv.y;
            acc[q].y += z.x*twv.y + z.y*twv.x;
        }
    }
#pragma unroll
    for (int q = 0; q < 4; q++) {
        int rem = h*16 + w*4 + q;
        g_C[((size_t)o*32 + rem)*256 + bci] = acc[q];
    }
}

// ---------------------------------------------------------------------------
// K3: einsum via g_W, TWO adjacent modes per block (512 blocks) for 2x ILP.
// D[bco][m] = (1/TX) sum_ci C[m][b,ci] W[m][ci,co], m = m0, m0+1.
// ---------------------------------------------------------------------------
__global__ void __launch_bounds__(256) k_einsum() {
    __shared__ float2 Cs[2][256];
    __shared__ float2 Ws[2][1024];
    const int tid = threadIdx.x;
    const int m0 = blockIdx.x * 2;
    Cs[0][tid] = g_C[(size_t)m0*256 + tid];
    Cs[1][tid] = g_C[(size_t)(m0+1)*256 + tid];
#pragma unroll
    for (int i = 0; i < 4; i++) {
        Ws[0][tid + i*256] = g_W[(size_t)m0*1024 + tid + i*256];
        Ws[1][tid + i*256] = g_W[(size_t)(m0+1)*1024 + tid + i*256];
    }
    __syncthreads();
    const int b = tid >> 5, co = tid & 31;
    float2 a0 = make_float2(0.f, 0.f);
    float2 a1 = make_float2(0.f, 0.f);
#pragma unroll
    for (int ci = 0; ci < 32; ci++) {
        float2 c0 = Cs[0][b*32 + ci];
        float2 c1 = Cs[1][b*32 + ci];
        float2 q0 = Ws[0][ci*32 + co];
        float2 q1 = Ws[1][ci*32 + co];
        a0.x += c0.x*q0.x - c0.y*q0.y;
        a0.y += c0.x*q0.y + c0.y*q0.x;
        a1.x += c1.x*q1.x - c1.y*q1.y;
        a1.y += c1.x*q1.y + c1.y*q1.x;
    }
    const float S = 1.0f / (128.0f * 256.0f);
    *(float4*)(g_D + (size_t)tid*1024 + m0) = make_float4(a0.x*S, a0.y*S, a1.x*S, a1.y*S);
}

// ---------------------------------------------------------------------------
// K4: inverse T (32 corner modes -> 128 t), radix split t = 8a + b.
// Block = half a bco (16 rem lines), 128 threads, grid 512.
// ---------------------------------------------------------------------------
__global__ void __launch_bounds__(128) k_inv_t() {
    __shared__ float2 tab[128];       // e^{+2pi i n/128}
    __shared__ float2 Ds[16][33];
    __shared__ float2 Hs[128][17];
    const int tid = threadIdx.x;
    {
        float sv, cv;
        __sincosf(6.283185307179586f * (float)tid * (1.0f/128.0f), &sv, &cv);
        tab[tid] = make_float2(cv, sv);
    }
    const int bco = blockIdx.x >> 1;
    const int h   = blockIdx.x & 1;

    const float2* src = g_D + (size_t)bco*1024;
#pragma unroll
    for (int i = 0; i < 4; i++) {
        int idx = tid + i*128;
        int j = idx >> 4, r = idx & 15;
        Ds[r][j] = src[j*32 + h*16 + r];
    }
    __syncthreads();

    const int w = tid >> 5, ln = tid & 31;
    const int l = ln >> 3, b = ln & 7;
    const int rem = w*4 + l;

    float2 S[16];
#pragma unroll
    for (int r = 0; r < 16; r++) {
        float2 d0 = Ds[rem][r];
        float2 d1 = Ds[rem][r+16];
        float2 t0 = tab[(b*r) & 127];
        float2 t1 = tab[(b*(r+112)) & 127];
        S[r].x = d0.x*t0.x - d0.y*t0.y + d1.x*t1.x - d1.y*t1.y;
        S[r].y = d0.x*t0.y + d0.y*t0.x + d1.x*t1.y + d1.y*t1.x;
    }
    fft16<1>(S);
#pragma unroll
    for (int a = 0; a < 16; a++) Hs[a*8 + b][rem] = S[a];
    __syncthreads();

    float4* dst = (float4*)(g_H + (size_t)bco*4096);
#pragma unroll
    for (int i = 0; i < 8; i++) {
        int idx = tid + i*128;
        int t = idx >> 3, q = idx & 7;
        float2 a0 = Hs[t][q*2], a1 = Hs[t][q*2 + 1];
        dst[t*16 + h*8 + q] = make_float4(a0.x, a0.y, a1.x, a1.y);
    }
}

// ---------------------------------------------------------------------------
// K5: inverse X (16 modes -> 256 x) + irfft over P, permuted store staging.
// ---------------------------------------------------------------------------
__global__ void __launch_bounds__(256) k_inv_xp(float* __restrict__ out) {
    __shared__ float2 tw[256];        // e^{+2pi i n/256}
    __shared__ float2 Hsm[8][32];
    __shared__ float2 gb[8][2][264];
    const int tid = threadIdx.x;
    {
        float sv, cv;
        __sincosf(6.283185307179586f * (float)tid * (1.0f/256.0f), &sv, &cv);
        tw[tid] = make_float2(cv, sv);
    }
    const int bco = blockIdx.x >> 4;
    const int t0  = (blockIdx.x & 15) << 3;
    Hsm[tid>>5][tid&31] = g_H[((size_t)bco*T_ + t0 + (tid>>5))*32 + (tid&31)];
    __syncthreads();

    const int w  = tid >> 5;
    const int ln = tid & 31;
    const int b_ = ln & 15;
    const int kp = ln >> 4;

    float2 v[16];
#pragma unroll
    for (int k = 0; k < 16; k++)
        v[k] = cmulf(Hsm[w][k*2 + kp], tw[k*b_]);
    fft16<1>(v);
    const int pbase = (b_ >> 3) + (b_ & 7)*33;
#pragma unroll
    for (int a = 0; a < 16; a++)
        gb[w][kp][pbase + 2*a] = v[a];
    __syncwarp();

    float f[24];
    const float TH = 1.0f / 3.0f;
    const float SQ3 = 1.7320508075688772f;
#pragma unroll
    for (int j = 0; j < 8; j++) {
        float2 g0 = gb[w][0][ln + 33*j];
        float2 g1 = gb[w][1][ln + 33*j];
        float r = g0.x;
        f[3*j+0] = (r + 2.f*g1.x) * TH;
        f[3*j+1] = (r - g1.x - SQ3*g1.y) * TH;
        f[3*j+2] = (r - g1.x + SQ3*g1.y) * TH;
    }
    float4* op = (float4*)(out + ((size_t)bco*T_ + t0 + w)*768 + 24*ln);
#pragma unroll
    for (int q = 0; q < 6; q++)
        op[q] = make_float4(f[4*q], f[4*q+1], f[4*q+2], f[4*q+3]);
}

extern "C" void kernel_launch(void* const* d_in, const int* in_sizes, int n_in,
                              void* d_out, int out_size) {
    const float* x   = (const float*)d_in[0];
    const float* w1r = (const float*)d_in[1];
    const float* w1i = (const float*)d_in[2];
    const float* w2r = (const float*)d_in[3];
    const float* w2i = (const float*)d_in[4];
    float* out = (float*)d_out;

    k_fwd_px<<<5120, 256>>>(x, w1r, w1i, w2r, w2i);  // fwd_px + merged weight transpose
    k_fwd_t <<<512, 128>>>();
    k_einsum<<<512, 256>>>();
    k_inv_t <<<512, 128>>>();
    k_inv_xp<<<4096, 256>>>(out);
}